// round 8
// baseline (speedup 1.0000x reference)
#include <cuda_runtime.h>
#include <cuda_bf16.h>
#include <math.h>
#include <stdint.h>

#define B_  2
#define S_  2048
#define D_  1024
#define H_  16
#define HD_ 64
#define M_  (B_ * S_)        // 4096
#define BHS (B_ * H_ * S_ * HD_)

// Scratch (device globals — no allocation inside kernel_launch)
__device__ float g_q[BHS];
__device__ float g_k[BHS];
__device__ float g_v[BHS];
__device__ float g_ctx[M_ * D_];

// ---------------------------------------------------------------------------
// helpers
// ---------------------------------------------------------------------------

// bf16 mma: D += A(16x16) * B(16x8)
__device__ __forceinline__ void mma16(float* d, const uint32_t* a, const uint32_t* b) {
    asm volatile(
        "mma.sync.aligned.m16n8k16.row.col.f32.bf16.bf16.f32 "
        "{%0,%1,%2,%3}, {%4,%5,%6,%7}, {%8,%9}, {%0,%1,%2,%3};\n"
        : "+f"(d[0]), "+f"(d[1]), "+f"(d[2]), "+f"(d[3])
        : "r"(a[0]), "r"(a[1]), "r"(a[2]), "r"(a[3]),
          "r"(b[0]), "r"(b[1]));
}

__device__ __forceinline__ void ldsm4(uint32_t& t0, uint32_t& t1,
                                      uint32_t& t2, uint32_t& t3,
                                      const void* p) {
    uint32_t saddr = (uint32_t)__cvta_generic_to_shared(p);
    asm volatile("ldmatrix.sync.aligned.m8n8.x4.shared.b16 "
                 "{%0,%1,%2,%3}, [%4];"
                 : "=r"(t0), "=r"(t1), "=r"(t2), "=r"(t3) : "r"(saddr));
}

__device__ __forceinline__ void ldsm4t(uint32_t& t0, uint32_t& t1,
                                       uint32_t& t2, uint32_t& t3,
                                       const void* p) {
    uint32_t saddr = (uint32_t)__cvta_generic_to_shared(p);
    asm volatile("ldmatrix.sync.aligned.m8n8.x4.trans.shared.b16 "
                 "{%0,%1,%2,%3}, [%4];"
                 : "=r"(t0), "=r"(t1), "=r"(t2), "=r"(t3) : "r"(saddr));
}

// split two floats into packed bf16x2 hi and lo words (element 0 = lower half)
__device__ __forceinline__ void split2(float x0, float x1,
                                       uint32_t& hi, uint32_t& lo) {
    __nv_bfloat16 h0 = __float2bfloat16_rn(x0);
    __nv_bfloat16 h1 = __float2bfloat16_rn(x1);
    __nv_bfloat16 l0 = __float2bfloat16_rn(x0 - __bfloat162float(h0));
    __nv_bfloat16 l1 = __float2bfloat16_rn(x1 - __bfloat162float(h1));
    __nv_bfloat162 hp = __halves2bfloat162(h0, h1);
    __nv_bfloat162 lp = __halves2bfloat162(l0, l1);
    hi = *reinterpret_cast<uint32_t*>(&hp);
    lo = *reinterpret_cast<uint32_t*>(&lp);
}

// ---------------------------------------------------------------------------
// GEMM via 3-term bf16 split: C[M,N] = A[M,K] @ W + bias  (fp32-class accuracy)
//  (unchanged from R5)
// ---------------------------------------------------------------------------
#define AW 20   // Ah/Al row stride in words (32 bf16 = 16 words + 4 pad)
#define BW 72   // Bh/Bl row stride in bf16 (64 + 8 pad); 144 B, 16B-aligned

template <bool HEADWISE>
__global__ __launch_bounds__(256)
void gemm_bf3(const float* __restrict__ A, const float* __restrict__ W,
              const float* __restrict__ bias, float* __restrict__ C,
              int K, int N) {
    __shared__ __align__(16) uint32_t Ah[128][AW];
    __shared__ __align__(16) uint32_t Al[128][AW];
    __shared__ __align__(16) __nv_bfloat16 Bh[32][BW];
    __shared__ __align__(16) __nv_bfloat16 Bl[32][BW];

    const int tid  = threadIdx.x;
    const int lane = tid & 31, wid = tid >> 5;
    const int grp  = lane >> 2, tg = lane & 3;
    const int wm   = wid >> 1, wn = wid & 1;        // 4 x 2 warp grid
    const int m0   = blockIdx.x * 128, n0 = blockIdx.y * 64;

    float acc[2][4][4];
    #pragma unroll
    for (int mi = 0; mi < 2; mi++)
        #pragma unroll
        for (int ni = 0; ni < 4; ni++)
            #pragma unroll
            for (int r = 0; r < 4; r++) acc[mi][ni][r] = 0.f;

    for (int kt = 0; kt < K; kt += 32) {
        #pragma unroll
        for (int j = 0; j < 4; j++) {
            int f = j * 256 + tid;
            int r = f >> 3, c = f & 7;
            float4 v = *(const float4*)(A + (size_t)(m0 + r) * K + kt + c * 4);
            uint32_t h0, l0, h1, l1;
            split2(v.x, v.y, h0, l0);
            split2(v.z, v.w, h1, l1);
            Ah[r][2 * c]     = h0;  Ah[r][2 * c + 1] = h1;
            Al[r][2 * c]     = l0;  Al[r][2 * c + 1] = l1;
        }
        #pragma unroll
        for (int j = 0; j < 2; j++) {
            int f = j * 256 + tid;
            int r = f >> 4, c4 = (f & 15) * 4;
            const float* src = HEADWISE
                ? W + ((size_t)(n0 >> 6) * K + kt + r) * 64 + c4
                : W + (size_t)(kt + r) * N + n0 + c4;
            float4 v = *(const float4*)src;
            uint32_t h0, l0, h1, l1;
            split2(v.x, v.y, h0, l0);
            split2(v.z, v.w, h1, l1);
            *(uint32_t*)&Bh[r][c4]     = h0;  *(uint32_t*)&Bh[r][c4 + 2] = h1;
            *(uint32_t*)&Bl[r][c4]     = l0;  *(uint32_t*)&Bl[r][c4 + 2] = l1;
        }
        __syncthreads();

        #pragma unroll
        for (int kk = 0; kk < 32; kk += 16) {
            const int w = kk >> 1;
            uint32_t fah[2][4], fal[2][4];
            #pragma unroll
            for (int mi = 0; mi < 2; mi++) {
                int r0 = wm * 32 + mi * 16;
                fah[mi][0] = Ah[r0 + grp][w + tg];
                fah[mi][1] = Ah[r0 + grp + 8][w + tg];
                fah[mi][2] = Ah[r0 + grp][w + tg + 4];
                fah[mi][3] = Ah[r0 + grp + 8][w + tg + 4];
                fal[mi][0] = Al[r0 + grp][w + tg];
                fal[mi][1] = Al[r0 + grp + 8][w + tg];
                fal[mi][2] = Al[r0 + grp][w + tg + 4];
                fal[mi][3] = Al[r0 + grp + 8][w + tg + 4];
            }
            uint32_t fbh[4][2], fbl[4][2];
            {
                int g = lane >> 3, r = lane & 7;
                int krow = kk + (g & 1) * 8 + r;
                #pragma unroll
                for (int nblk = 0; nblk < 2; nblk++) {
                    int col = wn * 32 + nblk * 16 + (g >> 1) * 8;
                    uint32_t t0, t1, t2, t3;
                    ldsm4t(t0, t1, t2, t3, &Bh[krow][col]);
                    fbh[nblk * 2][0] = t0;  fbh[nblk * 2][1] = t1;
                    fbh[nblk * 2 + 1][0] = t2;  fbh[nblk * 2 + 1][1] = t3;
                    ldsm4t(t0, t1, t2, t3, &Bl[krow][col]);
                    fbl[nblk * 2][0] = t0;  fbl[nblk * 2][1] = t1;
                    fbl[nblk * 2 + 1][0] = t2;  fbl[nblk * 2 + 1][1] = t3;
                }
            }
            #pragma unroll
            for (int mi = 0; mi < 2; mi++)
                #pragma unroll
                for (int ni = 0; ni < 4; ni++) {
                    mma16(acc[mi][ni], fah[mi], fbh[ni]);
                    mma16(acc[mi][ni], fah[mi], fbl[ni]);
                    mma16(acc[mi][ni], fal[mi], fbh[ni]);
                }
        }
        __syncthreads();
    }

    #pragma unroll
    for (int mi = 0; mi < 2; mi++) {
        #pragma unroll
        for (int ni = 0; ni < 4; ni++) {
            int n  = n0 + wn * 32 + ni * 8 + tg * 2;
            float b0 = bias[n], b1 = bias[n + 1];
            #pragma unroll
            for (int half = 0; half < 2; half++) {
                int m = m0 + wm * 32 + mi * 16 + grp + half * 8;
                float v0 = acc[mi][ni][half * 2 + 0] + b0;
                float v1 = acc[mi][ni][half * 2 + 1] + b1;
                if (HEADWISE) {
                    int bb = m / S_, s = m - bb * S_;
                    int hh = n >> 6, k = n & 63;
                    float* dst = C + (((size_t)(bb * H_ + hh)) * S_ + s) * HD_ + k;
                    dst[0] = v0; dst[1] = v1;
                } else {
                    C[(size_t)m * N + n]     = v0;
                    C[(size_t)m * N + n + 1] = v1;
                }
            }
        }
    }
}

// ---------------------------------------------------------------------------
// Flash attention — 3-term bf16 split (fp32-class), all fragments via ldmatrix.
// 128 q rows per CTA, 64-row K/V tiles. 8 warps 4(M)x2(N), warp = 32q x 32keys.
// Scale folded into Q at load. P split to bf16 hi/lo in softmax write-back.
// ---------------------------------------------------------------------------
#define QW 72                       // bf16 row stride (144 B; ldmatrix-aligned)
#define AP 68                       // fp32 score row stride

// smem byte offsets (all 16B-aligned)
#define OFF_QH   0                          // bf16 [128][72]  18432
#define OFF_QL   18432
#define OFF_PH   36864                      // bf16 [128][72]
#define OFF_PL   55296
#define OFF_KH   73728                      // bf16 [64][72]    9216
#define OFF_KL   82944
#define OFF_VH   92160
#define OFF_VL   101376
#define OFF_PS   110592                     // fp32 [128][68]  34816
#define OFF_ROW  145408                     // fp32 [128]        512
#define ATTN_SMEM 145920

__global__ __launch_bounds__(256)
void attn_tc(float* __restrict__ ctx) {
    extern __shared__ __align__(16) char smx[];
    __nv_bfloat16* qh = (__nv_bfloat16*)(smx + OFF_QH);
    __nv_bfloat16* ql = (__nv_bfloat16*)(smx + OFF_QL);
    __nv_bfloat16* ph = (__nv_bfloat16*)(smx + OFF_PH);
    __nv_bfloat16* pl = (__nv_bfloat16*)(smx + OFF_PL);
    __nv_bfloat16* kh = (__nv_bfloat16*)(smx + OFF_KH);
    __nv_bfloat16* kl = (__nv_bfloat16*)(smx + OFF_KL);
    __nv_bfloat16* vh = (__nv_bfloat16*)(smx + OFF_VH);
    __nv_bfloat16* vl = (__nv_bfloat16*)(smx + OFF_VL);
    float* ps     = (float*)(smx + OFF_PS);
    float* rowbuf = (float*)(smx + OFF_ROW);

    const int tid  = threadIdx.x;
    const int lane = tid & 31, wid = tid >> 5;
    const int grp  = lane >> 2, tg = lane & 3;
    const int wm   = wid >> 1, wn = wid & 1;
    const int bh   = blockIdx.y;
    const int b    = bh >> 4, h = bh & 15;
    const int s0   = blockIdx.x * 128;

    const float* Qp = g_q + (size_t)bh * S_ * HD_;
    const float* Kp = g_k + (size_t)bh * S_ * HD_;
    const float* Vp = g_v + (size_t)bh * S_ * HD_;

    const float scale = 0.125f;          // 1/sqrt(64), folded into Q

    // ldmatrix source offsets (computed once)
    const int a_row = lane & 15;               // + m-tile base
    const int a_col = (lane >> 4) << 3;        // + kk
    const int bk_n  = ((lane >> 4) << 3) + (lane & 7);       // K non-trans: n offset
    const int bk_k  = ((lane >> 3) & 1) << 3;                // K non-trans: k offset
    const int bv_k  = (((lane >> 3) & 1) << 3) + (lane & 7); // V trans: k-row offset
    const int bv_n  = (lane >> 4) << 3;                      // V trans: n offset

    // Q tile (128 x 64): scale, split, store bf16 hi/lo
    #pragma unroll
    for (int j = 0; j < 8; j++) {
        int f = j * 256 + tid;
        int r = f >> 4, c4 = (f & 15) * 4;
        float4 v = *(const float4*)(Qp + (size_t)(s0 + r) * HD_ + c4);
        uint32_t h0, l0, h1, l1;
        split2(v.x * scale, v.y * scale, h0, l0);
        split2(v.z * scale, v.w * scale, h1, l1);
        *(uint2*)&qh[r * QW + c4] = make_uint2(h0, h1);
        *(uint2*)&ql[r * QW + c4] = make_uint2(l0, l1);
    }

    float mrun = -1e30f, lrun = 0.f;     // softmax state: row = tid>>1
    float octx[2][4][4];
    #pragma unroll
    for (int mi = 0; mi < 2; mi++)
        #pragma unroll
        for (int ni = 0; ni < 4; ni++)
            #pragma unroll
            for (int r = 0; r < 4; r++) octx[mi][ni][r] = 0.f;

    for (int kt = 0; kt < S_; kt += 64) {
        __syncthreads();                 // prior PV done with kh/kl/vh/vl
        #pragma unroll
        for (int j = 0; j < 4; j++) {
            int f = j * 256 + tid;
            int r = f >> 4, c4 = (f & 15) * 4;
            float4 kv = *(const float4*)(Kp + (size_t)(kt + r) * HD_ + c4);
            uint32_t h0, l0, h1, l1;
            split2(kv.x, kv.y, h0, l0);
            split2(kv.z, kv.w, h1, l1);
            *(uint2*)&kh[r * QW + c4] = make_uint2(h0, h1);
            *(uint2*)&kl[r * QW + c4] = make_uint2(l0, l1);
            float4 vv = *(const float4*)(Vp + (size_t)(kt + r) * HD_ + c4);
            split2(vv.x, vv.y, h0, l0);
            split2(vv.z, vv.w, h1, l1);
            *(uint2*)&vh[r * QW + c4] = make_uint2(h0, h1);
            *(uint2*)&vl[r * QW + c4] = make_uint2(l0, l1);
        }
        __syncthreads();

        // S = Q K^T  (3-term bf16)
        float sacc[2][4][4];
        #pragma unroll
        for (int mi = 0; mi < 2; mi++)
            #pragma unroll
            for (int ni = 0; ni < 4; ni++)
                #pragma unroll
                for (int r = 0; r < 4; r++) sacc[mi][ni][r] = 0.f;

        #pragma unroll
        for (int kk = 0; kk < 64; kk += 16) {
            uint32_t fah[2][4], fal[2][4];
            #pragma unroll
            for (int mi = 0; mi < 2; mi++) {
                int r0 = wm * 32 + mi * 16 + a_row;
                ldsm4(fah[mi][0], fah[mi][1], fah[mi][2], fah[mi][3],
                      &qh[r0 * QW + kk + a_col]);
                ldsm4(fal[mi][0], fal[mi][1], fal[mi][2], fal[mi][3],
                      &ql[r0 * QW + kk + a_col]);
            }
            uint32_t fbh[4][2], fbl[4][2];
            #pragma unroll
            for (int nblk = 0; nblk < 2; nblk++) {
                int n = wn * 32 + nblk * 16 + bk_n;
                uint32_t t0, t1, t2, t3;
                ldsm4(t0, t1, t2, t3, &kh[n * QW + kk + bk_k]);
                fbh[nblk*2][0] = t0;   fbh[nblk*2][1] = t1;
                fbh[nblk*2+1][0] = t2; fbh[nblk*2+1][1] = t3;
                ldsm4(t0, t1, t2, t3, &kl[n * QW + kk + bk_k]);
                fbl[nblk*2][0] = t0;   fbl[nblk*2][1] = t1;
                fbl[nblk*2+1][0] = t2; fbl[nblk*2+1][1] = t3;
            }
            #pragma unroll
            for (int mi = 0; mi < 2; mi++)
                #pragma unroll
                for (int ni = 0; ni < 4; ni++) {
                    mma16(sacc[mi][ni], fah[mi], fbh[ni]);
                    mma16(sacc[mi][ni], fah[mi], fbl[ni]);
                    mma16(sacc[mi][ni], fal[mi], fbh[ni]);
                }
        }
        // scores -> smem (fp32)
        #pragma unroll
        for (int mi = 0; mi < 2; mi++) {
            int r = wm * 32 + mi * 16 + grp;
            #pragma unroll
            for (int ni = 0; ni < 4; ni++) {
                int c = wn * 32 + ni * 8 + tg * 2;
                *(float2*)(ps + r*AP + c)     = make_float2(sacc[mi][ni][0], sacc[mi][ni][1]);
                *(float2*)(ps + (r+8)*AP + c) = make_float2(sacc[mi][ni][2], sacc[mi][ni][3]);
            }
        }
        __syncthreads();

        // online softmax: 2 threads per row, 32 cols each; P split hi/lo
        {
            int row = tid >> 1, seg = (tid & 1) * 32;
            float* pr = ps + row * AP + seg;
            float rm = -1e30f;
            #pragma unroll
            for (int j = 0; j < 32; j++) rm = fmaxf(rm, pr[j]);
            rm = fmaxf(rm, __shfl_xor_sync(0xffffffffu, rm, 1, 2));
            float mn    = fmaxf(mrun, rm);
            float alpha = __expf(mrun - mn);
            float rs = 0.f;
            __nv_bfloat16* phr = ph + row * QW + seg;
            __nv_bfloat16* plr = pl + row * QW + seg;
            #pragma unroll
            for (int j = 0; j < 32; j += 2) {
                float p0 = __expf(pr[j]     - mn);
                float p1 = __expf(pr[j + 1] - mn);
                rs += p0 + p1;
                uint32_t hp, lp;
                split2(p0, p1, hp, lp);
                *(uint32_t*)&phr[j] = hp;
                *(uint32_t*)&plr[j] = lp;
            }
            rs += __shfl_xor_sync(0xffffffffu, rs, 1, 2);
            lrun = lrun * alpha + rs;
            mrun = mn;
            if (!(tid & 1)) rowbuf[row] = alpha;
        }
        __syncthreads();

        // rescale running ctx
        #pragma unroll
        for (int mi = 0; mi < 2; mi++) {
            int r0 = wm * 32 + mi * 16;
            float a0 = rowbuf[r0 + grp];
            float a1 = rowbuf[r0 + grp + 8];
            #pragma unroll
            for (int ni = 0; ni < 4; ni++) {
                octx[mi][ni][0] *= a0; octx[mi][ni][1] *= a0;
                octx[mi][ni][2] *= a1; octx[mi][ni][3] *= a1;
            }
        }

        // octx += P @ V  (3-term bf16; V via trans ldmatrix)
        #pragma unroll
        for (int kk = 0; kk < 64; kk += 16) {
            uint32_t fah[2][4], fal[2][4];
            #pragma unroll
            for (int mi = 0; mi < 2; mi++) {
                int r0 = wm * 32 + mi * 16 + a_row;
                ldsm4(fah[mi][0], fah[mi][1], fah[mi][2], fah[mi][3],
                      &ph[r0 * QW + kk + a_col]);
                ldsm4(fal[mi][0], fal[mi][1], fal[mi][2], fal[mi][3],
                      &pl[r0 * QW + kk + a_col]);
            }
            uint32_t fbh[4][2], fbl[4][2];
            #pragma unroll
            for (int nblk = 0; nblk < 2; nblk++) {
                int col = wn * 32 + nblk * 16 + bv_n;
                int kr  = kk + bv_k;
                uint32_t t0, t1, t2, t3;
                ldsm4t(t0, t1, t2, t3, &vh[kr * QW + col]);
                fbh[nblk*2][0] = t0;   fbh[nblk*2][1] = t1;
                fbh[nblk*2+1][0] = t2; fbh[nblk*2+1][1] = t3;
                ldsm4t(t0, t1, t2, t3, &vl[kr * QW + col]);
                fbl[nblk*2][0] = t0;   fbl[nblk*2][1] = t1;
                fbl[nblk*2+1][0] = t2; fbl[nblk*2+1][1] = t3;
            }
            #pragma unroll
            for (int mi = 0; mi < 2; mi++)
                #pragma unroll
                for (int ni = 0; ni < 4; ni++) {
                    mma16(octx[mi][ni], fah[mi], fbh[ni]);
                    mma16(octx[mi][ni], fah[mi], fbl[ni]);
                    mma16(octx[mi][ni], fal[mi], fbh[ni]);
                }
        }
    }

    __syncthreads();
    if (!(tid & 1)) rowbuf[tid >> 1] = 1.0f / lrun;
    __syncthreads();

    // write ctx in [B, S, H*HD] layout
    #pragma unroll
    for (int mi = 0; mi < 2; mi++) {
        int r0 = wm * 32 + mi * 16;
        float l0 = rowbuf[r0 + grp];
        float l1 = rowbuf[r0 + grp + 8];
        int sg0 = s0 + r0 + grp;
        #pragma unroll
        for (int ni = 0; ni < 4; ni++) {
            int c = wn * 32 + ni * 8 + tg * 2;
            *(float2*)(ctx + ((size_t)(b * S_ + sg0    )) * D_ + h * HD_ + c)
                = make_float2(octx[mi][ni][0] * l0, octx[mi][ni][1] * l0);
            *(float2*)(ctx + ((size_t)(b * S_ + sg0 + 8)) * D_ + h * HD_ + c)
                = make_float2(octx[mi][ni][2] * l1, octx[mi][ni][3] * l1);
        }
    }
}

// ---------------------------------------------------------------------------

extern "C" void kernel_launch(void* const* d_in, const int* in_sizes, int n_in,
                              void* d_out, int out_size) {
    const float* query = (const float*)d_in[0];
    const float* key   = (const float*)d_in[1];
    const float* value = (const float*)d_in[2];
    const float* Wq    = (const float*)d_in[3];
    const float* bq    = (const float*)d_in[4];
    const float* Wk    = (const float*)d_in[5];
    const float* bk    = (const float*)d_in[6];
    const float* Wv    = (const float*)d_in[7];
    const float* bv    = (const float*)d_in[8];
    const float* Wo    = (const float*)d_in[9];
    const float* bo    = (const float*)d_in[10];
    float* out = (float*)d_out;

    float *qb, *kb, *vb, *ctx;
    cudaGetSymbolAddress((void**)&qb,  g_q);
    cudaGetSymbolAddress((void**)&kb,  g_k);
    cudaGetSymbolAddress((void**)&vb,  g_v);
    cudaGetSymbolAddress((void**)&ctx, g_ctx);

    cudaFuncSetAttribute(attn_tc,
                         cudaFuncAttributeMaxDynamicSharedMemorySize,
                         ATTN_SMEM);

    dim3 blk(256);
    dim3 pGrid(M_ / 128, D_ / 64);   // 32 x 16

    // Q/K/V projections — 3-term bf16 (fp32-class accuracy)
    gemm_bf3<true ><<<pGrid, blk>>>(query, Wq, bq, qb, D_, D_);
    gemm_bf3<true ><<<pGrid, blk>>>(key,   Wk, bk, kb, D_, D_);
    gemm_bf3<true ><<<pGrid, blk>>>(value, Wv, bv, vb, D_, D_);

    // Attention — 3-term bf16 mma
    dim3 aGrid(S_ / 128, B_ * H_);   // (16, 32)
    attn_tc<<<aGrid, blk, ATTN_SMEM>>>(ctx);

    // Output projection — 3-term bf16
    gemm_bf3<false><<<pGrid, blk>>>(ctx, Wo, bo, out, D_, D_);
}

// round 9
// speedup vs baseline: 1.3090x; 1.3090x over previous
#include <cuda_runtime.h>
#include <cuda_bf16.h>
#include <math.h>
#include <stdint.h>

#define B_  2
#define S_  2048
#define D_  1024
#define H_  16
#define HD_ 64
#define M_  (B_ * S_)        // 4096
#define BHS (B_ * H_ * S_ * HD_)

// Scratch (device globals — no allocation inside kernel_launch)
__device__ float g_q[BHS];
__device__ float g_k[BHS];
__device__ float g_v[BHS];
__device__ float g_ctx[M_ * D_];

// ---------------------------------------------------------------------------
// helpers
// ---------------------------------------------------------------------------

// bf16 mma: D += A(16x16) * B(16x8)
__device__ __forceinline__ void mma16(float* d, const uint32_t* a, const uint32_t* b) {
    asm volatile(
        "mma.sync.aligned.m16n8k16.row.col.f32.bf16.bf16.f32 "
        "{%0,%1,%2,%3}, {%4,%5,%6,%7}, {%8,%9}, {%0,%1,%2,%3};\n"
        : "+f"(d[0]), "+f"(d[1]), "+f"(d[2]), "+f"(d[3])
        : "r"(a[0]), "r"(a[1]), "r"(a[2]), "r"(a[3]),
          "r"(b[0]), "r"(b[1]));
}

__device__ __forceinline__ void ldsm4(uint32_t& t0, uint32_t& t1,
                                      uint32_t& t2, uint32_t& t3,
                                      const void* p) {
    uint32_t saddr = (uint32_t)__cvta_generic_to_shared(p);
    asm volatile("ldmatrix.sync.aligned.m8n8.x4.shared.b16 "
                 "{%0,%1,%2,%3}, [%4];"
                 : "=r"(t0), "=r"(t1), "=r"(t2), "=r"(t3) : "r"(saddr));
}

__device__ __forceinline__ void ldsm4t(uint32_t& t0, uint32_t& t1,
                                       uint32_t& t2, uint32_t& t3,
                                       const void* p) {
    uint32_t saddr = (uint32_t)__cvta_generic_to_shared(p);
    asm volatile("ldmatrix.sync.aligned.m8n8.x4.trans.shared.b16 "
                 "{%0,%1,%2,%3}, [%4];"
                 : "=r"(t0), "=r"(t1), "=r"(t2), "=r"(t3) : "r"(saddr));
}

// split two floats into packed bf16x2 hi and lo words (element 0 = lower half)
__device__ __forceinline__ void split2(float x0, float x1,
                                       uint32_t& hi, uint32_t& lo) {
    __nv_bfloat16 h0 = __float2bfloat16_rn(x0);
    __nv_bfloat16 h1 = __float2bfloat16_rn(x1);
    __nv_bfloat16 l0 = __float2bfloat16_rn(x0 - __bfloat162float(h0));
    __nv_bfloat16 l1 = __float2bfloat16_rn(x1 - __bfloat162float(h1));
    __nv_bfloat162 hp = __halves2bfloat162(h0, h1);
    __nv_bfloat162 lp = __halves2bfloat162(l0, l1);
    hi = *reinterpret_cast<uint32_t*>(&hp);
    lo = *reinterpret_cast<uint32_t*>(&lp);
}

// ---------------------------------------------------------------------------
// GEMM via 3-term bf16 split: C[M,N] = A[M,K] @ W + bias  (unchanged)
// ---------------------------------------------------------------------------
#define AW 20
#define BW 72

template <bool HEADWISE>
__global__ __launch_bounds__(256)
void gemm_bf3(const float* __restrict__ A, const float* __restrict__ W,
              const float* __restrict__ bias, float* __restrict__ C,
              int K, int N) {
    __shared__ __align__(16) uint32_t Ah[128][AW];
    __shared__ __align__(16) uint32_t Al[128][AW];
    __shared__ __align__(16) __nv_bfloat16 Bh[32][BW];
    __shared__ __align__(16) __nv_bfloat16 Bl[32][BW];

    const int tid  = threadIdx.x;
    const int lane = tid & 31, wid = tid >> 5;
    const int grp  = lane >> 2, tg = lane & 3;
    const int wm   = wid >> 1, wn = wid & 1;
    const int m0   = blockIdx.x * 128, n0 = blockIdx.y * 64;

    float acc[2][4][4];
    #pragma unroll
    for (int mi = 0; mi < 2; mi++)
        #pragma unroll
        for (int ni = 0; ni < 4; ni++)
            #pragma unroll
            for (int r = 0; r < 4; r++) acc[mi][ni][r] = 0.f;

    for (int kt = 0; kt < K; kt += 32) {
        #pragma unroll
        for (int j = 0; j < 4; j++) {
            int f = j * 256 + tid;
            int r = f >> 3, c = f & 7;
            float4 v = *(const float4*)(A + (size_t)(m0 + r) * K + kt + c * 4);
            uint32_t h0, l0, h1, l1;
            split2(v.x, v.y, h0, l0);
            split2(v.z, v.w, h1, l1);
            Ah[r][2 * c]     = h0;  Ah[r][2 * c + 1] = h1;
            Al[r][2 * c]     = l0;  Al[r][2 * c + 1] = l1;
        }
        #pragma unroll
        for (int j = 0; j < 2; j++) {
            int f = j * 256 + tid;
            int r = f >> 4, c4 = (f & 15) * 4;
            const float* src = HEADWISE
                ? W + ((size_t)(n0 >> 6) * K + kt + r) * 64 + c4
                : W + (size_t)(kt + r) * N + n0 + c4;
            float4 v = *(const float4*)src;
            uint32_t h0, l0, h1, l1;
            split2(v.x, v.y, h0, l0);
            split2(v.z, v.w, h1, l1);
            *(uint32_t*)&Bh[r][c4]     = h0;  *(uint32_t*)&Bh[r][c4 + 2] = h1;
            *(uint32_t*)&Bl[r][c4]     = l0;  *(uint32_t*)&Bl[r][c4 + 2] = l1;
        }
        __syncthreads();

        #pragma unroll
        for (int kk = 0; kk < 32; kk += 16) {
            const int w = kk >> 1;
            uint32_t fah[2][4], fal[2][4];
            #pragma unroll
            for (int mi = 0; mi < 2; mi++) {
                int r0 = wm * 32 + mi * 16;
                fah[mi][0] = Ah[r0 + grp][w + tg];
                fah[mi][1] = Ah[r0 + grp + 8][w + tg];
                fah[mi][2] = Ah[r0 + grp][w + tg + 4];
                fah[mi][3] = Ah[r0 + grp + 8][w + tg + 4];
                fal[mi][0] = Al[r0 + grp][w + tg];
                fal[mi][1] = Al[r0 + grp + 8][w + tg];
                fal[mi][2] = Al[r0 + grp][w + tg + 4];
                fal[mi][3] = Al[r0 + grp + 8][w + tg + 4];
            }
            uint32_t fbh[4][2], fbl[4][2];
            {
                int g = lane >> 3, r = lane & 7;
                int krow = kk + (g & 1) * 8 + r;
                #pragma unroll
                for (int nblk = 0; nblk < 2; nblk++) {
                    int col = wn * 32 + nblk * 16 + (g >> 1) * 8;
                    uint32_t t0, t1, t2, t3;
                    ldsm4t(t0, t1, t2, t3, &Bh[krow][col]);
                    fbh[nblk * 2][0] = t0;  fbh[nblk * 2][1] = t1;
                    fbh[nblk * 2 + 1][0] = t2;  fbh[nblk * 2 + 1][1] = t3;
                    ldsm4t(t0, t1, t2, t3, &Bl[krow][col]);
                    fbl[nblk * 2][0] = t0;  fbl[nblk * 2][1] = t1;
                    fbl[nblk * 2 + 1][0] = t2;  fbl[nblk * 2 + 1][1] = t3;
                }
            }
            #pragma unroll
            for (int mi = 0; mi < 2; mi++)
                #pragma unroll
                for (int ni = 0; ni < 4; ni++) {
                    mma16(acc[mi][ni], fah[mi], fbh[ni]);
                    mma16(acc[mi][ni], fah[mi], fbl[ni]);
                    mma16(acc[mi][ni], fal[mi], fbh[ni]);
                }
        }
        __syncthreads();
    }

    #pragma unroll
    for (int mi = 0; mi < 2; mi++) {
        #pragma unroll
        for (int ni = 0; ni < 4; ni++) {
            int n  = n0 + wn * 32 + ni * 8 + tg * 2;
            float b0 = bias[n], b1 = bias[n + 1];
            #pragma unroll
            for (int half = 0; half < 2; half++) {
                int m = m0 + wm * 32 + mi * 16 + grp + half * 8;
                float v0 = acc[mi][ni][half * 2 + 0] + b0;
                float v1 = acc[mi][ni][half * 2 + 1] + b1;
                if (HEADWISE) {
                    int bb = m / S_, s = m - bb * S_;
                    int hh = n >> 6, k = n & 63;
                    float* dst = C + (((size_t)(bb * H_ + hh)) * S_ + s) * HD_ + k;
                    dst[0] = v0; dst[1] = v1;
                } else {
                    C[(size_t)m * N + n]     = v0;
                    C[(size_t)m * N + n + 1] = v1;
                }
            }
        }
    }
}

// ---------------------------------------------------------------------------
// Flash attention — FA2-style register softmax, 3-term bf16, no P smem.
// 128 q rows per CTA, 64-row K/V tiles. 8 warps, warp = 16 q rows x 64 keys.
// C-fragment of QK^T reused directly as A-fragment of PV.
// ---------------------------------------------------------------------------
#define QW 72                       // bf16 row stride (144 B; ldmatrix-aligned)

#define OFF_QH   0                          // bf16 [128][72]  18432
#define OFF_QL   18432
#define OFF_KH   36864                      // bf16 [64][72]    9216
#define OFF_KL   46080
#define OFF_VH   55296
#define OFF_VL   64512
#define ATTN_SMEM 73728

__global__ __launch_bounds__(256, 2)
void attn_tc(float* __restrict__ ctx) {
    extern __shared__ __align__(16) char smx[];
    __nv_bfloat16* qh = (__nv_bfloat16*)(smx + OFF_QH);
    __nv_bfloat16* ql = (__nv_bfloat16*)(smx + OFF_QL);
    __nv_bfloat16* kh = (__nv_bfloat16*)(smx + OFF_KH);
    __nv_bfloat16* kl = (__nv_bfloat16*)(smx + OFF_KL);
    __nv_bfloat16* vh = (__nv_bfloat16*)(smx + OFF_VH);
    __nv_bfloat16* vl = (__nv_bfloat16*)(smx + OFF_VL);

    const int tid  = threadIdx.x;
    const int lane = tid & 31, wid = tid >> 5;
    const int grp  = lane >> 2, tg = lane & 3;
    const int bh   = blockIdx.y;
    const int b    = bh >> 4, h = bh & 15;
    const int s0   = blockIdx.x * 128;
    const int mrow = wid * 16;               // warp's q-row base

    const float* Qp = g_q + (size_t)bh * S_ * HD_;
    const float* Kp = g_k + (size_t)bh * S_ * HD_;
    const float* Vp = g_v + (size_t)bh * S_ * HD_;

    const float scale = 0.125f;              // 1/sqrt(64), folded into Q

    // ldmatrix source offsets
    const int a_row = lane & 15;
    const int a_col = (lane >> 4) << 3;
    const int bk_n  = ((lane >> 4) << 3) + (lane & 7);       // K non-trans
    const int bk_k  = ((lane >> 3) & 1) << 3;
    const int bv_k  = (((lane >> 3) & 1) << 3) + (lane & 7); // V trans
    const int bv_n  = (lane >> 4) << 3;

    // Q tile (128 x 64): scale, split, store bf16 hi/lo
    #pragma unroll
    for (int j = 0; j < 8; j++) {
        int f = j * 256 + tid;
        int r = f >> 4, c4 = (f & 15) * 4;
        float4 v = *(const float4*)(Qp + (size_t)(s0 + r) * HD_ + c4);
        uint32_t h0, l0, h1, l1;
        split2(v.x * scale, v.y * scale, h0, l0);
        split2(v.z * scale, v.w * scale, h1, l1);
        *(uint2*)&qh[r * QW + c4] = make_uint2(h0, h1);
        *(uint2*)&ql[r * QW + c4] = make_uint2(l0, l1);
    }

    // softmax state: row0 = mrow+grp, row1 = mrow+grp+8
    float m0 = -1e30f, m1 = -1e30f, l0s = 0.f, l1s = 0.f;
    float octx[8][4];
    #pragma unroll
    for (int ni = 0; ni < 8; ni++)
        #pragma unroll
        for (int r = 0; r < 4; r++) octx[ni][r] = 0.f;

    for (int kt = 0; kt < S_; kt += 64) {
        __syncthreads();                 // prior PV done reading vh/vl
        #pragma unroll
        for (int j = 0; j < 4; j++) {
            int f = j * 256 + tid;
            int r = f >> 4, c4 = (f & 15) * 4;
            float4 kv = *(const float4*)(Kp + (size_t)(kt + r) * HD_ + c4);
            uint32_t h0, l0, h1, l1;
            split2(kv.x, kv.y, h0, l0);
            split2(kv.z, kv.w, h1, l1);
            *(uint2*)&kh[r * QW + c4] = make_uint2(h0, h1);
            *(uint2*)&kl[r * QW + c4] = make_uint2(l0, l1);
            float4 vv = *(const float4*)(Vp + (size_t)(kt + r) * HD_ + c4);
            split2(vv.x, vv.y, h0, l0);
            split2(vv.z, vv.w, h1, l1);
            *(uint2*)&vh[r * QW + c4] = make_uint2(h0, h1);
            *(uint2*)&vl[r * QW + c4] = make_uint2(l0, l1);
        }
        __syncthreads();

        // ---- S = Q K^T : 8 n-tiles (64 keys), 3-term bf16 ----
        float sacc[8][4];
        #pragma unroll
        for (int ni = 0; ni < 8; ni++)
            #pragma unroll
            for (int r = 0; r < 4; r++) sacc[ni][r] = 0.f;

        #pragma unroll
        for (int kk = 0; kk < 64; kk += 16) {
            uint32_t fah[4], fal[4];
            ldsm4(fah[0], fah[1], fah[2], fah[3],
                  &qh[(mrow + a_row) * QW + kk + a_col]);
            ldsm4(fal[0], fal[1], fal[2], fal[3],
                  &ql[(mrow + a_row) * QW + kk + a_col]);
            #pragma unroll
            for (int nb = 0; nb < 4; nb++) {          // 2 n-tiles per ldsm4
                int n = nb * 16 + bk_n;
                uint32_t h0, h1, h2, h3, lo0, lo1, lo2, lo3;
                ldsm4(h0, h1, h2, h3, &kh[n * QW + kk + bk_k]);
                ldsm4(lo0, lo1, lo2, lo3, &kl[n * QW + kk + bk_k]);
                uint32_t bh0[2] = {h0, h1}, bh1[2] = {h2, h3};
                uint32_t bl0[2] = {lo0, lo1}, bl1[2] = {lo2, lo3};
                mma16(sacc[nb * 2],     fah, bh0);
                mma16(sacc[nb * 2],     fah, bl0);
                mma16(sacc[nb * 2],     fal, bh0);
                mma16(sacc[nb * 2 + 1], fah, bh1);
                mma16(sacc[nb * 2 + 1], fah, bl1);
                mma16(sacc[nb * 2 + 1], fal, bh1);
            }
        }

        // ---- register softmax (rows fully within warp) ----
        float rm0 = -1e30f, rm1 = -1e30f;
        #pragma unroll
        for (int ni = 0; ni < 8; ni++) {
            rm0 = fmaxf(rm0, fmaxf(sacc[ni][0], sacc[ni][1]));
            rm1 = fmaxf(rm1, fmaxf(sacc[ni][2], sacc[ni][3]));
        }
        rm0 = fmaxf(rm0, __shfl_xor_sync(0xffffffffu, rm0, 1, 4));
        rm0 = fmaxf(rm0, __shfl_xor_sync(0xffffffffu, rm0, 2, 4));
        rm1 = fmaxf(rm1, __shfl_xor_sync(0xffffffffu, rm1, 1, 4));
        rm1 = fmaxf(rm1, __shfl_xor_sync(0xffffffffu, rm1, 2, 4));

        float mn0 = fmaxf(m0, rm0), mn1 = fmaxf(m1, rm1);
        float al0 = __expf(m0 - mn0), al1 = __expf(m1 - mn1);
        m0 = mn0;  m1 = mn1;

        // exponentiate + split P to bf16 hi/lo packed (C-frag == A-frag layout)
        uint32_t p01h[8], p23h[8], p01l[8], p23l[8];
        float rs0 = 0.f, rs1 = 0.f;
        #pragma unroll
        for (int ni = 0; ni < 8; ni++) {
            float p0 = __expf(sacc[ni][0] - mn0);
            float p1 = __expf(sacc[ni][1] - mn0);
            float p2 = __expf(sacc[ni][2] - mn1);
            float p3 = __expf(sacc[ni][3] - mn1);
            rs0 += p0 + p1;  rs1 += p2 + p3;
            split2(p0, p1, p01h[ni], p01l[ni]);
            split2(p2, p3, p23h[ni], p23l[ni]);
        }
        rs0 += __shfl_xor_sync(0xffffffffu, rs0, 1, 4);
        rs0 += __shfl_xor_sync(0xffffffffu, rs0, 2, 4);
        rs1 += __shfl_xor_sync(0xffffffffu, rs1, 1, 4);
        rs1 += __shfl_xor_sync(0xffffffffu, rs1, 2, 4);
        l0s = l0s * al0 + rs0;
        l1s = l1s * al1 + rs1;

        // rescale running ctx
        #pragma unroll
        for (int ni = 0; ni < 8; ni++) {
            octx[ni][0] *= al0; octx[ni][1] *= al0;
            octx[ni][2] *= al1; octx[ni][3] *= al1;
        }

        // ---- octx += P @ V : k = 64 keys (4 k16 steps), 3-term ----
        #pragma unroll
        for (int s = 0; s < 4; s++) {
            uint32_t pah[4] = {p01h[2*s], p23h[2*s], p01h[2*s+1], p23h[2*s+1]};
            uint32_t pal[4] = {p01l[2*s], p23l[2*s], p01l[2*s+1], p23l[2*s+1]};
            int kr = s * 16 + bv_k;
            #pragma unroll
            for (int nb = 0; nb < 4; nb++) {          // 2 d-tiles per ldsm4t
                int col = nb * 16 + bv_n;
                uint32_t h0, h1, h2, h3, lo0, lo1, lo2, lo3;
                ldsm4t(h0, h1, h2, h3, &vh[kr * QW + col]);
                ldsm4t(lo0, lo1, lo2, lo3, &vl[kr * QW + col]);
                uint32_t bh0[2] = {h0, h1}, bh1[2] = {h2, h3};
                uint32_t bl0[2] = {lo0, lo1}, bl1[2] = {lo2, lo3};
                mma16(octx[nb * 2],     pah, bh0);
                mma16(octx[nb * 2],     pah, bl0);
                mma16(octx[nb * 2],     pal, bh0);
                mma16(octx[nb * 2 + 1], pah, bh1);
                mma16(octx[nb * 2 + 1], pah, bl1);
                mma16(octx[nb * 2 + 1], pal, bh1);
            }
        }
    }

    // epilogue: normalize, write ctx in [B, S, H*HD] layout
    float inv0 = 1.0f / l0s, inv1 = 1.0f / l1s;
    int sg0 = s0 + mrow + grp;
    #pragma unroll
    for (int ni = 0; ni < 8; ni++) {
        int c = ni * 8 + tg * 2;
        *(float2*)(ctx + ((size_t)(b * S_ + sg0    )) * D_ + h * HD_ + c)
            = make_float2(octx[ni][0] * inv0, octx[ni][1] * inv0);
        *(float2*)(ctx + ((size_t)(b * S_ + sg0 + 8)) * D_ + h * HD_ + c)
            = make_float2(octx[ni][2] * inv1, octx[ni][3] * inv1);
    }
}

// ---------------------------------------------------------------------------

extern "C" void kernel_launch(void* const* d_in, const int* in_sizes, int n_in,
                              void* d_out, int out_size) {
    const float* query = (const float*)d_in[0];
    const float* key   = (const float*)d_in[1];
    const float* value = (const float*)d_in[2];
    const float* Wq    = (const float*)d_in[3];
    const float* bq    = (const float*)d_in[4];
    const float* Wk    = (const float*)d_in[5];
    const float* bk    = (const float*)d_in[6];
    const float* Wv    = (const float*)d_in[7];
    const float* bv    = (const float*)d_in[8];
    const float* Wo    = (const float*)d_in[9];
    const float* bo    = (const float*)d_in[10];
    float* out = (float*)d_out;

    float *qb, *kb, *vb, *ctx;
    cudaGetSymbolAddress((void**)&qb,  g_q);
    cudaGetSymbolAddress((void**)&kb,  g_k);
    cudaGetSymbolAddress((void**)&vb,  g_v);
    cudaGetSymbolAddress((void**)&ctx, g_ctx);

    cudaFuncSetAttribute(attn_tc,
                         cudaFuncAttributeMaxDynamicSharedMemorySize,
                         ATTN_SMEM);

    dim3 blk(256);
    dim3 pGrid(M_ / 128, D_ / 64);   // 32 x 16

    // Q/K/V projections — 3-term bf16 (fp32-class accuracy)
    gemm_bf3<true ><<<pGrid, blk>>>(query, Wq, bq, qb, D_, D_);
    gemm_bf3<true ><<<pGrid, blk>>>(key,   Wk, bk, kb, D_, D_);
    gemm_bf3<true ><<<pGrid, blk>>>(value, Wv, bv, vb, D_, D_);

    // Attention — 3-term bf16, register softmax
    dim3 aGrid(S_ / 128, B_ * H_);   // (16, 32)
    attn_tc<<<aGrid, blk, ATTN_SMEM>>>(ctx);

    // Output projection — 3-term bf16
    gemm_bf3<false><<<pGrid, blk>>>(ctx, Wo, bo, out, D_, D_);
}

// round 13
// speedup vs baseline: 1.3119x; 1.0022x over previous
#include <cuda_runtime.h>
#include <cuda_bf16.h>
#include <math.h>
#include <stdint.h>

#define B_  2
#define S_  2048
#define D_  1024
#define H_  16
#define HD_ 64
#define M_  (B_ * S_)        // 4096
#define BHS (B_ * H_ * S_ * HD_)

#define NW_X  (M_ * D_ / 2)        // words per input/proj/ctx plane  (2M)
#define NW_W  (H_ * D_ * HD_ / 2)  // words per weight plane          (512K)

// Pre-split bf16 planes (packed bf16x2 words). No allocation in kernel_launch.
__device__ uint32_t g_xqh[NW_X], g_xql[NW_X];   // inputs
__device__ uint32_t g_xkh[NW_X], g_xkl[NW_X];
__device__ uint32_t g_xvh[NW_X], g_xvl[NW_X];
__device__ uint32_t g_wqh[NW_W], g_wql[NW_W];   // weights
__device__ uint32_t g_wkh[NW_W], g_wkl[NW_W];
__device__ uint32_t g_wvh[NW_W], g_wvl[NW_W];
__device__ uint32_t g_woh[NW_W], g_wol[NW_W];
__device__ uint32_t g_pqh[NW_X], g_pql[NW_X];   // projected q/k/v ([B,H,S,HD])
__device__ uint32_t g_pkh[NW_X], g_pkl[NW_X];
__device__ uint32_t g_pvh[NW_X], g_pvl[NW_X];
__device__ uint32_t g_ch [NW_X], g_cl [NW_X];   // ctx ([B,S,D])

// ---------------------------------------------------------------------------
// helpers
// ---------------------------------------------------------------------------
__device__ __forceinline__ void mma16(float* d, const uint32_t* a, const uint32_t* b) {
    asm volatile(
        "mma.sync.aligned.m16n8k16.row.col.f32.bf16.bf16.f32 "
        "{%0,%1,%2,%3}, {%4,%5,%6,%7}, {%8,%9}, {%0,%1,%2,%3};\n"
        : "+f"(d[0]), "+f"(d[1]), "+f"(d[2]), "+f"(d[3])
        : "r"(a[0]), "r"(a[1]), "r"(a[2]), "r"(a[3]),
          "r"(b[0]), "r"(b[1]));
}

__device__ __forceinline__ void ldsm4(uint32_t& t0, uint32_t& t1,
                                      uint32_t& t2, uint32_t& t3,
                                      const void* p) {
    uint32_t saddr = (uint32_t)__cvta_generic_to_shared(p);
    asm volatile("ldmatrix.sync.aligned.m8n8.x4.shared.b16 "
                 "{%0,%1,%2,%3}, [%4];"
                 : "=r"(t0), "=r"(t1), "=r"(t2), "=r"(t3) : "r"(saddr));
}

__device__ __forceinline__ void ldsm4t(uint32_t& t0, uint32_t& t1,
                                       uint32_t& t2, uint32_t& t3,
                                       const void* p) {
    uint32_t saddr = (uint32_t)__cvta_generic_to_shared(p);
    asm volatile("ldmatrix.sync.aligned.m8n8.x4.trans.shared.b16 "
                 "{%0,%1,%2,%3}, [%4];"
                 : "=r"(t0), "=r"(t1), "=r"(t2), "=r"(t3) : "r"(saddr));
}

__device__ __forceinline__ void split2(float x0, float x1,
                                       uint32_t& hi, uint32_t& lo) {
    __nv_bfloat16 h0 = __float2bfloat16_rn(x0);
    __nv_bfloat16 h1 = __float2bfloat16_rn(x1);
    __nv_bfloat16 l0 = __float2bfloat16_rn(x0 - __bfloat162float(h0));
    __nv_bfloat16 l1 = __float2bfloat16_rn(x1 - __bfloat162float(h1));
    __nv_bfloat162 hp = __halves2bfloat162(h0, h1);
    __nv_bfloat162 lp = __halves2bfloat162(l0, l1);
    hi = *reinterpret_cast<uint32_t*>(&hp);
    lo = *reinterpret_cast<uint32_t*>(&lp);
}

// ---------------------------------------------------------------------------
// Prep: split fp32 array into packed bf16 hi/lo planes.
// ---------------------------------------------------------------------------
__global__ void split_kernel(const float* __restrict__ src,
                             uint32_t* __restrict__ hi,
                             uint32_t* __restrict__ lo, int nwords) {
    int i = blockIdx.x * blockDim.x + threadIdx.x;
    if (i < nwords) {
        float2 v = ((const float2*)src)[i];
        uint32_t h, l;
        split2(v.x, v.y, h, l);
        hi[i] = h;
        lo[i] = l;
    }
}

// ---------------------------------------------------------------------------
// GEMM on pre-split planes, 3-term bf16: C = (A @ W + bias) * scale
//  HEADWISE=true : W planes are [H,K,64]; output -> hi/lo planes in [B,H,S,HD].
//  HEADWISE=false: W planes [K,N]; output -> fp32 Cf [M,N].
//  Tile 128x64, BK=32, 256 threads (8 warps 4x2, 32x32/warp).
//  A frags via ldmatrix (non-trans), B frags via ldmatrix.trans.
// ---------------------------------------------------------------------------
#define AWB 40   // A smem row stride in bf16 (32 + 8 pad) = 80 B
#define BW  72   // B smem row stride in bf16 (64 + 8 pad) = 144 B

template <bool HEADWISE>
__global__ __launch_bounds__(256)
void gemm_pre(const uint32_t* __restrict__ Ah_g, const uint32_t* __restrict__ Al_g,
              const uint32_t* __restrict__ Wh_g, const uint32_t* __restrict__ Wl_g,
              const float* __restrict__ bias, float scale,
              uint32_t* __restrict__ Ch, uint32_t* __restrict__ Cl,
              float* __restrict__ Cf, int K, int N) {
    __shared__ __align__(16) __nv_bfloat16 Ah[128][AWB];
    __shared__ __align__(16) __nv_bfloat16 Al[128][AWB];
    __shared__ __align__(16) __nv_bfloat16 Bh[32][BW];
    __shared__ __align__(16) __nv_bfloat16 Bl[32][BW];

    const int tid  = threadIdx.x;
    const int lane = tid & 31, wid = tid >> 5;
    const int grp  = lane >> 2, tg = lane & 3;
    const int wm   = wid >> 1, wn = wid & 1;
    const int m0   = blockIdx.x * 128, n0 = blockIdx.y * 64;
    const int KW   = K / 2;                       // words per A row

    // ldmatrix offsets
    const int a_row = lane & 15;
    const int a_col = (lane >> 4) << 3;

    float acc[2][4][4];
    #pragma unroll
    for (int mi = 0; mi < 2; mi++)
        #pragma unroll
        for (int ni = 0; ni < 4; ni++)
            #pragma unroll
            for (int r = 0; r < 4; r++) acc[mi][ni][r] = 0.f;

    for (int kt = 0; kt < K; kt += 32) {
        // A tile: 128 rows x 16 words per plane (4 uint4 chunks per row)
        #pragma unroll
        for (int j = 0; j < 2; j++) {
            int f = j * 256 + tid;
            int r = f >> 2, c = (f & 3) * 4;      // c: word offset
            size_t gidx = (size_t)(m0 + r) * KW + (kt >> 1) + c;
            *(uint4*)&Ah[r][c * 2] = *(const uint4*)(Ah_g + gidx);
            *(uint4*)&Al[r][c * 2] = *(const uint4*)(Al_g + gidx);
        }
        // B tile: 32 rows x 32 words per plane (8 uint4 chunks per row)
        {
            int r = tid >> 3, c = (tid & 7) * 4;  // c: word offset
            size_t gidx = HEADWISE
                ? ((size_t)(n0 >> 6) * K + kt + r) * 32 + c
                : (size_t)(kt + r) * (N >> 1) + (n0 >> 1) + c;
            *(uint4*)&Bh[r][c * 2] = *(const uint4*)(Wh_g + gidx);
            *(uint4*)&Bl[r][c * 2] = *(const uint4*)(Wl_g + gidx);
        }
        __syncthreads();

        #pragma unroll
        for (int kk = 0; kk < 32; kk += 16) {
            uint32_t fah[2][4], fal[2][4];
            #pragma unroll
            for (int mi = 0; mi < 2; mi++) {
                int r0 = wm * 32 + mi * 16 + a_row;
                ldsm4(fah[mi][0], fah[mi][1], fah[mi][2], fah[mi][3],
                      &Ah[r0][kk + a_col]);
                ldsm4(fal[mi][0], fal[mi][1], fal[mi][2], fal[mi][3],
                      &Al[r0][kk + a_col]);
            }
            uint32_t fbh[4][2], fbl[4][2];
            {
                int g = lane >> 3, r = lane & 7;
                int krow = kk + (g & 1) * 8 + r;
                #pragma unroll
                for (int nblk = 0; nblk < 2; nblk++) {
                    int col = wn * 32 + nblk * 16 + (g >> 1) * 8;
                    uint32_t t0, t1, t2, t3;
                    ldsm4t(t0, t1, t2, t3, &Bh[krow][col]);
                    fbh[nblk * 2][0] = t0;  fbh[nblk * 2][1] = t1;
                    fbh[nblk * 2 + 1][0] = t2;  fbh[nblk * 2 + 1][1] = t3;
                    ldsm4t(t0, t1, t2, t3, &Bl[krow][col]);
                    fbl[nblk * 2][0] = t0;  fbl[nblk * 2][1] = t1;
                    fbl[nblk * 2 + 1][0] = t2;  fbl[nblk * 2 + 1][1] = t3;
                }
            }
            #pragma unroll
            for (int mi = 0; mi < 2; mi++)
                #pragma unroll
                for (int ni = 0; ni < 4; ni++) {
                    mma16(acc[mi][ni], fah[mi], fbh[ni]);
                    mma16(acc[mi][ni], fah[mi], fbl[ni]);
                    mma16(acc[mi][ni], fal[mi], fbh[ni]);
                }
        }
        __syncthreads();
    }

    // Epilogue
    #pragma unroll
    for (int mi = 0; mi < 2; mi++) {
        #pragma unroll
        for (int ni = 0; ni < 4; ni++) {
            int n  = n0 + wn * 32 + ni * 8 + tg * 2;
            float b0 = bias[n], b1 = bias[n + 1];
            #pragma unroll
            for (int half = 0; half < 2; half++) {
                int m = m0 + wm * 32 + mi * 16 + grp + half * 8;
                float v0 = (acc[mi][ni][half * 2 + 0] + b0) * scale;
                float v1 = (acc[mi][ni][half * 2 + 1] + b1) * scale;
                if (HEADWISE) {
                    int bb = m / S_, s = m - bb * S_;
                    int hh = n >> 6, k = n & 63;
                    size_t idx = (((size_t)(bb * H_ + hh)) * S_ + s) * 32 + (k >> 1);
                    uint32_t h, l;
                    split2(v0, v1, h, l);
                    Ch[idx] = h;
                    Cl[idx] = l;
                } else {
                    Cf[(size_t)m * N + n]     = v0;
                    Cf[(size_t)m * N + n + 1] = v1;
                }
            }
        }
    }
}

// ---------------------------------------------------------------------------
// Flash attention — FA2 register softmax, 3-term bf16, pre-split operands.
// 128 q rows/CTA, 64-row K/V tiles, 8 warps, warp = 16 q rows x 64 keys.
// Q/K/V arrive as bf16 hi/lo planes (scale pre-folded into Q) — load = copy.
// ctx written as bf16 hi/lo planes for the output projection.
// ---------------------------------------------------------------------------
#define QW 72

#define OFF_QH   0                          // bf16 [128][72]  18432
#define OFF_QL   18432
#define OFF_KH   36864                      // bf16 [64][72]    9216
#define OFF_KL   46080
#define OFF_VH   55296
#define OFF_VL   64512
#define ATTN_SMEM 73728

__global__ __launch_bounds__(256, 2)
void attn_tc(const uint32_t* __restrict__ pqh, const uint32_t* __restrict__ pql,
             const uint32_t* __restrict__ pkh, const uint32_t* __restrict__ pkl,
             const uint32_t* __restrict__ pvh, const uint32_t* __restrict__ pvl,
             uint32_t* __restrict__ ch, uint32_t* __restrict__ cl) {
    extern __shared__ __align__(16) char smx[];
    __nv_bfloat16* qh = (__nv_bfloat16*)(smx + OFF_QH);
    __nv_bfloat16* ql = (__nv_bfloat16*)(smx + OFF_QL);
    __nv_bfloat16* kh = (__nv_bfloat16*)(smx + OFF_KH);
    __nv_bfloat16* kl = (__nv_bfloat16*)(smx + OFF_KL);
    __nv_bfloat16* vh = (__nv_bfloat16*)(smx + OFF_VH);
    __nv_bfloat16* vl = (__nv_bfloat16*)(smx + OFF_VL);

    const int tid  = threadIdx.x;
    const int lane = tid & 31, wid = tid >> 5;
    const int grp  = lane >> 2, tg = lane & 3;
    const int bh   = blockIdx.y;
    const int b    = bh >> 4, h = bh & 15;
    const int s0   = blockIdx.x * 128;
    const int mrow = wid * 16;

    const size_t headbase = (size_t)bh * S_ * 32;   // words

    // ldmatrix offsets
    const int a_row = lane & 15;
    const int a_col = (lane >> 4) << 3;
    const int bk_n  = ((lane >> 4) << 3) + (lane & 7);
    const int bk_k  = ((lane >> 3) & 1) << 3;
    const int bv_k  = (((lane >> 3) & 1) << 3) + (lane & 7);
    const int bv_n  = (lane >> 4) << 3;

    // Q tile: 128 rows x 32 words per plane = 1024 uint4 (8 chunks per row)
    #pragma unroll
    for (int j = 0; j < 4; j++) {
        int f = j * 256 + tid;
        int r = f >> 3, c = (f & 7) * 4;           // word offset
        size_t gidx = headbase + (size_t)(s0 + r) * 32 + c;
        *(uint4*)&qh[r * QW + c * 2] = *(const uint4*)(pqh + gidx);
        *(uint4*)&ql[r * QW + c * 2] = *(const uint4*)(pql + gidx);
    }

    float m0 = -1e30f, m1 = -1e30f, l0s = 0.f, l1s = 0.f;
    float octx[8][4];
    #pragma unroll
    for (int ni = 0; ni < 8; ni++)
        #pragma unroll
        for (int r = 0; r < 4; r++) octx[ni][r] = 0.f;

    for (int kt = 0; kt < S_; kt += 64) {
        __syncthreads();
        // K/V tiles: 64 rows x 32 words per plane = 512 uint4 (8 chunks per row)
        #pragma unroll
        for (int j = 0; j < 2; j++) {
            int f = j * 256 + tid;
            int r = f >> 3, c = (f & 7) * 4;       // word offset
            size_t gidx = headbase + (size_t)(kt + r) * 32 + c;
            *(uint4*)&kh[r * QW + c * 2] = *(const uint4*)(pkh + gidx);
            *(uint4*)&kl[r * QW + c * 2] = *(const uint4*)(pkl + gidx);
            *(uint4*)&vh[r * QW + c * 2] = *(const uint4*)(pvh + gidx);
            *(uint4*)&vl[r * QW + c * 2] = *(const uint4*)(pvl + gidx);
        }
        __syncthreads();

        // ---- S = Q K^T ----
        float sacc[8][4];
        #pragma unroll
        for (int ni = 0; ni < 8; ni++)
            #pragma unroll
            for (int r = 0; r < 4; r++) sacc[ni][r] = 0.f;

        #pragma unroll
        for (int kk = 0; kk < 64; kk += 16) {
            uint32_t fah[4], fal[4];
            ldsm4(fah[0], fah[1], fah[2], fah[3],
                  &qh[(mrow + a_row) * QW + kk + a_col]);
            ldsm4(fal[0], fal[1], fal[2], fal[3],
                  &ql[(mrow + a_row) * QW + kk + a_col]);
            #pragma unroll
            for (int nb = 0; nb < 4; nb++) {
                int n = nb * 16 + bk_n;
                uint32_t h0, h1, h2, h3, lo0, lo1, lo2, lo3;
                ldsm4(h0, h1, h2, h3, &kh[n * QW + kk + bk_k]);
                ldsm4(lo0, lo1, lo2, lo3, &kl[n * QW + kk + bk_k]);
                uint32_t bh0[2] = {h0, h1}, bh1[2] = {h2, h3};
                uint32_t bl0[2] = {lo0, lo1}, bl1[2] = {lo2, lo3};
                mma16(sacc[nb * 2],     fah, bh0);
                mma16(sacc[nb * 2],     fah, bl0);
                mma16(sacc[nb * 2],     fal, bh0);
                mma16(sacc[nb * 2 + 1], fah, bh1);
                mma16(sacc[nb * 2 + 1], fah, bl1);
                mma16(sacc[nb * 2 + 1], fal, bh1);
            }
        }

        // ---- register softmax ----
        float rm0 = -1e30f, rm1 = -1e30f;
        #pragma unroll
        for (int ni = 0; ni < 8; ni++) {
            rm0 = fmaxf(rm0, fmaxf(sacc[ni][0], sacc[ni][1]));
            rm1 = fmaxf(rm1, fmaxf(sacc[ni][2], sacc[ni][3]));
        }
        rm0 = fmaxf(rm0, __shfl_xor_sync(0xffffffffu, rm0, 1, 4));
        rm0 = fmaxf(rm0, __shfl_xor_sync(0xffffffffu, rm0, 2, 4));
        rm1 = fmaxf(rm1, __shfl_xor_sync(0xffffffffu, rm1, 1, 4));
        rm1 = fmaxf(rm1, __shfl_xor_sync(0xffffffffu, rm1, 2, 4));

        float mn0 = fmaxf(m0, rm0), mn1 = fmaxf(m1, rm1);
        float al0 = __expf(m0 - mn0), al1 = __expf(m1 - mn1);
        m0 = mn0;  m1 = mn1;

        uint32_t p01h[8], p23h[8], p01l[8], p23l[8];
        float rs0 = 0.f, rs1 = 0.f;
        #pragma unroll
        for (int ni = 0; ni < 8; ni++) {
            float p0 = __expf(sacc[ni][0] - mn0);
            float p1 = __expf(sacc[ni][1] - mn0);
            float p2 = __expf(sacc[ni][2] - mn1);
            float p3 = __expf(sacc[ni][3] - mn1);
            rs0 += p0 + p1;  rs1 += p2 + p3;
            split2(p0, p1, p01h[ni], p01l[ni]);
            split2(p2, p3, p23h[ni], p23l[ni]);
        }
        rs0 += __shfl_xor_sync(0xffffffffu, rs0, 1, 4);
        rs0 += __shfl_xor_sync(0xffffffffu, rs0, 2, 4);
        rs1 += __shfl_xor_sync(0xffffffffu, rs1, 1, 4);
        rs1 += __shfl_xor_sync(0xffffffffu, rs1, 2, 4);
        l0s = l0s * al0 + rs0;
        l1s = l1s * al1 + rs1;

        #pragma unroll
        for (int ni = 0; ni < 8; ni++) {
            octx[ni][0] *= al0; octx[ni][1] *= al0;
            octx[ni][2] *= al1; octx[ni][3] *= al1;
        }

        // ---- octx += P @ V ----
        #pragma unroll
        for (int s = 0; s < 4; s++) {
            uint32_t pah[4] = {p01h[2*s], p23h[2*s], p01h[2*s+1], p23h[2*s+1]};
            uint32_t pal[4] = {p01l[2*s], p23l[2*s], p01l[2*s+1], p23l[2*s+1]};
            int kr = s * 16 + bv_k;
            #pragma unroll
            for (int nb = 0; nb < 4; nb++) {
                int col = nb * 16 + bv_n;
                uint32_t h0, h1, h2, h3, lo0, lo1, lo2, lo3;
                ldsm4t(h0, h1, h2, h3, &vh[kr * QW + col]);
                ldsm4t(lo0, lo1, lo2, lo3, &vl[kr * QW + col]);
                uint32_t bh0[2] = {h0, h1}, bh1[2] = {h2, h3};
                uint32_t bl0[2] = {lo0, lo1}, bl1[2] = {lo2, lo3};
                mma16(octx[nb * 2],     pah, bh0);
                mma16(octx[nb * 2],     pah, bl0);
                mma16(octx[nb * 2],     pal, bh0);
                mma16(octx[nb * 2 + 1], pah, bh1);
                mma16(octx[nb * 2 + 1], pah, bl1);
                mma16(octx[nb * 2 + 1], pal, bh1);
            }
        }
    }

    // epilogue: normalize, split, write ctx hi/lo planes ([B,S,D] packed)
    float inv0 = 1.0f / l0s, inv1 = 1.0f / l1s;
    int sg0 = s0 + mrow + grp;
    #pragma unroll
    for (int ni = 0; ni < 8; ni++) {
        int c = ni * 8 + tg * 2;
        size_t idx0 = ((size_t)(b * S_ + sg0    )) * 512 + h * 32 + (c >> 1);
        size_t idx1 = ((size_t)(b * S_ + sg0 + 8)) * 512 + h * 32 + (c >> 1);
        uint32_t hw, lw;
        split2(octx[ni][0] * inv0, octx[ni][1] * inv0, hw, lw);
        ch[idx0] = hw;  cl[idx0] = lw;
        split2(octx[ni][2] * inv1, octx[ni][3] * inv1, hw, lw);
        ch[idx1] = hw;  cl[idx1] = lw;
    }
}

// ---------------------------------------------------------------------------

extern "C" void kernel_launch(void* const* d_in, const int* in_sizes, int n_in,
                              void* d_out, int out_size) {
    const float* query = (const float*)d_in[0];
    const float* key   = (const float*)d_in[1];
    const float* value = (const float*)d_in[2];
    const float* Wq    = (const float*)d_in[3];
    const float* bq    = (const float*)d_in[4];
    const float* Wk    = (const float*)d_in[5];
    const float* bk    = (const float*)d_in[6];
    const float* Wv    = (const float*)d_in[7];
    const float* bv    = (const float*)d_in[8];
    const float* Wo    = (const float*)d_in[9];
    const float* bo    = (const float*)d_in[10];
    float* out = (float*)d_out;

    uint32_t *xqh, *xql, *xkh, *xkl, *xvh, *xvl;
    uint32_t *wqh, *wql, *wkh, *wkl, *wvh, *wvl, *woh, *wol;
    uint32_t *pqh, *pql, *pkh, *pkl, *pvh, *pvl, *ch, *cl;
    cudaGetSymbolAddress((void**)&xqh, g_xqh);  cudaGetSymbolAddress((void**)&xql, g_xql);
    cudaGetSymbolAddress((void**)&xkh, g_xkh);  cudaGetSymbolAddress((void**)&xkl, g_xkl);
    cudaGetSymbolAddress((void**)&xvh, g_xvh);  cudaGetSymbolAddress((void**)&xvl, g_xvl);
    cudaGetSymbolAddress((void**)&wqh, g_wqh);  cudaGetSymbolAddress((void**)&wql, g_wql);
    cudaGetSymbolAddress((void**)&wkh, g_wkh);  cudaGetSymbolAddress((void**)&wkl, g_wkl);
    cudaGetSymbolAddress((void**)&wvh, g_wvh);  cudaGetSymbolAddress((void**)&wvl, g_wvl);
    cudaGetSymbolAddress((void**)&woh, g_woh);  cudaGetSymbolAddress((void**)&wol, g_wol);
    cudaGetSymbolAddress((void**)&pqh, g_pqh);  cudaGetSymbolAddress((void**)&pql, g_pql);
    cudaGetSymbolAddress((void**)&pkh, g_pkh);  cudaGetSymbolAddress((void**)&pkl, g_pkl);
    cudaGetSymbolAddress((void**)&pvh, g_pvh);  cudaGetSymbolAddress((void**)&pvl, g_pvl);
    cudaGetSymbolAddress((void**)&ch,  g_ch);   cudaGetSymbolAddress((void**)&cl,  g_cl);

    cudaFuncSetAttribute(attn_tc,
                         cudaFuncAttributeMaxDynamicSharedMemorySize,
                         ATTN_SMEM);

    // 1) pre-split inputs + weights
    split_kernel<<<NW_X / 256, 256>>>(query, xqh, xql, NW_X);
    split_kernel<<<NW_X / 256, 256>>>(key,   xkh, xkl, NW_X);
    split_kernel<<<NW_X / 256, 256>>>(value, xvh, xvl, NW_X);
    split_kernel<<<NW_W / 256, 256>>>(Wq, wqh, wql, NW_W);
    split_kernel<<<NW_W / 256, 256>>>(Wk, wkh, wkl, NW_W);
    split_kernel<<<NW_W / 256, 256>>>(Wv, wvh, wvl, NW_W);
    split_kernel<<<NW_W / 256, 256>>>(Wo, woh, wol, NW_W);

    dim3 blk(256);
    dim3 pGrid(M_ / 128, D_ / 64);   // 32 x 16

    // 2) projections (scale folded into Q)
    gemm_pre<true ><<<pGrid, blk>>>(xqh, xql, wqh, wql, bq, 0.125f,
                                    pqh, pql, nullptr, D_, D_);
    gemm_pre<true ><<<pGrid, blk>>>(xkh, xkl, wkh, wkl, bk, 1.0f,
                                    pkh, pkl, nullptr, D_, D_);
    gemm_pre<true ><<<pGrid, blk>>>(xvh, xvl, wvh, wvl, bv, 1.0f,
                                    pvh, pvl, nullptr, D_, D_);

    // 3) attention
    dim3 aGrid(S_ / 128, B_ * H_);   // (16, 32)
    attn_tc<<<aGrid, blk, ATTN_SMEM>>>(pqh, pql, pkh, pkl, pvh, pvl, ch, cl);

    // 4) output projection -> fp32 out
    gemm_pre<false><<<pGrid, blk>>>(ch, cl, woh, wol, bo, 1.0f,
                                    nullptr, nullptr, out, D_, D_);
}